// round 6
// baseline (speedup 1.0000x reference)
#include <cuda_runtime.h>
#include <cstdint>

// x [B=32, T=4096, N=256] float32 -> z same shape.
#define BB 32
#define TT 4096
#define NN 256
#define BN (BB * NN)          // 8192 chains
#define NQ (BN / 4)           // 2048 quads of chains
#define CHUNK 64
#define NC (TT / CHUNK)       // 64 chunks
#define REFR 5

// Static scratch (~6.5 MB)
__device__ ulonglong2 g_mask2[NC][BN / 2];   // per-chain 64-bit sign masks (paired)
__device__ uint4      g_map4[NC][BN / 4];    // per-chain nibble-packed chunk map (u32)
__device__ uchar4     g_qin4[NC][BN / 4];    // incoming q per (chunk, chain)

// Byte-level automaton LUTs (blockDim.x == 256) — used by pass1 only.
// For byte b, incoming state k (0..7): greedy spikes, q_out = max(0, last-2).
// s_sel[b]: nibble k = q_out(k) (PRMT-selector-ready); s_byt[b]: byte k = q_out(k).
__device__ __forceinline__ void build_luts(uint32_t* s_sel, uint64_t* s_byt) {
    const uint32_t b = threadIdx.x;
    uint32_t sel = 0; uint64_t byt = 0;
    for (int k = 0; k < 8; ++k) {
        int pos = k, last = -3;
        while (pos < 8) {
            uint32_t m = b >> pos;
            if (!m) break;
            int s = pos + __ffs((int)m) - 1;
            last = s;
            pos = s + REFR + 1;
        }
        int q = last - 2; if (q < 0) q = 0;
        sel |= (uint32_t)q << (4 * k);
        byt |= (uint64_t)q << (8 * k);
    }
    s_sel[b] = sel; s_byt[b] = byt;
    __syncthreads();
}

// byte-packed (2 regs) -> nibble-packed u32 (q values are all <= 7)
__device__ __forceinline__ uint32_t nib_compress(uint32_t lo, uint32_t hi) {
    uint32_t t1 = lo | (lo >> 4);
    uint32_t t2 = hi | (hi >> 4);
    return __byte_perm(t1, 0, 0x4420) | (__byte_perm(t2, 0, 0x4420) << 16);
}

// Pass 1: per (chain-quad, chunk): read x, build 4 sign masks + 4 chunk maps.
__global__ void __launch_bounds__(256) pass1_mask_map(const float4* __restrict__ x4) {
    __shared__ uint32_t s_sel[256];
    __shared__ uint64_t s_byt[256];
    build_luts(s_sel, s_byt);

    int tid  = blockIdx.x * 256 + threadIdx.x;   // 0 .. NQ*NC-1
    int quad = tid & (NQ - 1);
    int c    = tid >> 11;                        // / NQ
    int b    = quad >> 6;                        // / (NN/4)
    int nq   = quad & 63;

    const float4* px = x4 + ((size_t)b * TT + (size_t)c * CHUNK) * (NN / 4) + nq;

    uint64_t m0 = 0, m1 = 0, m2 = 0, m3 = 0;
    uint32_t S0l, S0h, S1l, S1h, S2l, S2h, S3l, S3h;

    // byte 7 first (right fold: S = m7), then fold m6..m0 in.
    {
        uint32_t b0 = 0, b1 = 0, b2 = 0, b3 = 0;
#pragma unroll
        for (int i = 0; i < 8; ++i) {
            float4 v = px[(size_t)(56 + i) * (NN / 4)];
            if (v.x > 0.0f) b0 |= 1u << i;
            if (v.y > 0.0f) b1 |= 1u << i;
            if (v.z > 0.0f) b2 |= 1u << i;
            if (v.w > 0.0f) b3 |= 1u << i;
        }
        m0 |= (uint64_t)b0 << 56; m1 |= (uint64_t)b1 << 56;
        m2 |= (uint64_t)b2 << 56; m3 |= (uint64_t)b3 << 56;
        uint64_t t;
        t = s_byt[b0]; S0l = (uint32_t)t; S0h = (uint32_t)(t >> 32);
        t = s_byt[b1]; S1l = (uint32_t)t; S1h = (uint32_t)(t >> 32);
        t = s_byt[b2]; S2l = (uint32_t)t; S2h = (uint32_t)(t >> 32);
        t = s_byt[b3]; S3l = (uint32_t)t; S3h = (uint32_t)(t >> 32);
    }
#pragma unroll
    for (int j = 6; j >= 0; --j) {
        uint32_t b0 = 0, b1 = 0, b2 = 0, b3 = 0;
#pragma unroll
        for (int i = 0; i < 8; ++i) {
            float4 v = px[(size_t)(j * 8 + i) * (NN / 4)];
            if (v.x > 0.0f) b0 |= 1u << i;
            if (v.y > 0.0f) b1 |= 1u << i;
            if (v.z > 0.0f) b2 |= 1u << i;
            if (v.w > 0.0f) b3 |= 1u << i;
        }
        m0 |= (uint64_t)b0 << (8 * j); m1 |= (uint64_t)b1 << (8 * j);
        m2 |= (uint64_t)b2 << (8 * j); m3 |= (uint64_t)b3 << (8 * j);
        uint32_t sel, nl, nh;
        sel = s_sel[b0]; nl = __byte_perm(S0l, S0h, sel); nh = __byte_perm(S0l, S0h, sel >> 16); S0l = nl; S0h = nh;
        sel = s_sel[b1]; nl = __byte_perm(S1l, S1h, sel); nh = __byte_perm(S1l, S1h, sel >> 16); S1l = nl; S1h = nh;
        sel = s_sel[b2]; nl = __byte_perm(S2l, S2h, sel); nh = __byte_perm(S2l, S2h, sel >> 16); S2l = nl; S2h = nh;
        sel = s_sel[b3]; nl = __byte_perm(S3l, S3h, sel); nh = __byte_perm(S3l, S3h, sel >> 16); S3l = nl; S3h = nh;
    }

    g_mask2[c][quad * 2]     = make_ulonglong2(m0, m1);
    g_mask2[c][quad * 2 + 1] = make_ulonglong2(m2, m3);
    g_map4[c][quad] = make_uint4(nib_compress(S0l, S0h), nib_compress(S1l, S1h),
                                 nib_compress(S2l, S2h), nib_compress(S3l, S3h));
}

// Pass 2: per chain — chain the 64 nibble-packed chunk maps.
__global__ void __launch_bounds__(256) pass2_compose() {
    int bn = blockIdx.x * 256 + threadIdx.x;     // 0 .. BN-1
    const uint32_t* maps = (const uint32_t*)g_map4;   // [NC][BN]
    uint8_t* qin = (uint8_t*)g_qin4;
    uint32_t q = 0;
#pragma unroll
    for (int base = 0; base < NC; base += 16) {
        uint32_t m[16];
#pragma unroll
        for (int j = 0; j < 16; ++j) m[j] = maps[(base + j) * BN + bn];
#pragma unroll
        for (int j = 0; j < 16; ++j) {
            qin[(base + j) * BN + bn] = (uint8_t)q;
            q = (m[j] >> (q * 4)) & 7u;
        }
    }
}

// Greedy spike reconstruction, register-only. Bounded: <= 11 spikes per 64 steps.
__device__ __forceinline__ uint64_t rebuild_spikes(uint64_t mask, int pos) {
    uint64_t sp = 0;
    while (pos < CHUNK) {
        uint64_t m = mask >> pos;
        if (!m) break;
        int s = pos + __ffsll((long long)m) - 1;
        sp |= 1ull << s;
        pos = s + REFR + 1;
    }
    return sp;
}

// Pass 3: per (chain-quad, chunk): rebuild spikes in registers, write float4.
__global__ void __launch_bounds__(256) pass3_emit(float4* __restrict__ out4) {
    int tid  = blockIdx.x * 256 + threadIdx.x;
    int quad = tid & (NQ - 1);
    int c    = tid >> 11;
    int b    = quad >> 6;
    int nq   = quad & 63;

    ulonglong2 ma = g_mask2[c][quad * 2];
    ulonglong2 mb = g_mask2[c][quad * 2 + 1];
    uchar4 qv = g_qin4[c][quad];

    uint64_t sp0 = rebuild_spikes(ma.x, qv.x);
    uint64_t sp1 = rebuild_spikes(ma.y, qv.y);
    uint64_t sp2 = rebuild_spikes(mb.x, qv.z);
    uint64_t sp3 = rebuild_spikes(mb.y, qv.w);

    float4* po = out4 + ((size_t)b * TT + (size_t)c * CHUNK) * (NN / 4) + nq;
#pragma unroll
    for (int i = 0; i < CHUNK; ++i) {
        float4 v;
        v.x = __uint_as_float((uint32_t)((sp0 >> i) & 1u) * 0x3F800000u);
        v.y = __uint_as_float((uint32_t)((sp1 >> i) & 1u) * 0x3F800000u);
        v.z = __uint_as_float((uint32_t)((sp2 >> i) & 1u) * 0x3F800000u);
        v.w = __uint_as_float((uint32_t)((sp3 >> i) & 1u) * 0x3F800000u);
        po[(size_t)i * (NN / 4)] = v;
    }
}

extern "C" void kernel_launch(void* const* d_in, const int* in_sizes, int n_in,
                              void* d_out, int out_size) {
    (void)in_sizes; (void)n_in; (void)out_size;
    const float4* x4 = (const float4*)d_in[0];
    float4* out4 = (float4*)d_out;

    const int threads = 256;
    const int grid_big = (NQ * NC) / threads;    // 512 blocks
    const int grid_small = BN / threads;         // 32 blocks

    pass1_mask_map<<<grid_big, threads>>>(x4);
    pass2_compose<<<grid_small, threads>>>();
    pass3_emit<<<grid_big, threads>>>(out4);
}

// round 7
// speedup vs baseline: 1.3505x; 1.3505x over previous
#include <cuda_runtime.h>
#include <cstdint>

// x [B=32, T=4096, N=256] float32 -> z same shape.
#define BB 32
#define TT 4096
#define NN 256
#define BN (BB * NN)          // 8192 chains
#define NQ (BN / 4)           // 2048 quads of chains
#define CHUNK 64
#define NC (TT / CHUNK)       // 64 chunks
#define REFR 5

// Static scratch (~6.5 MB)
__device__ ulonglong2 g_mask2[NC][BN / 2];   // per-chain 64-bit sign masks (paired)
__device__ uint4      g_map4[NC][BN / 4];    // per-chain nibble-packed chunk map (u32)
__device__ uchar4     g_qin4[NC][BN / 4];    // incoming q per (chunk, chain)

// Byte-level automaton LUTs (blockDim.x == 256) — used by pass1 only.
// For byte b, incoming state k (0..7): greedy spikes, q_out = max(0, last-2).
// s_sel[b]: nibble k = q_out(k) (PRMT-selector-ready); s_byt[b]: byte k = q_out(k).
__device__ __forceinline__ void build_luts(uint32_t* s_sel, uint64_t* s_byt) {
    const uint32_t b = threadIdx.x;
    uint32_t sel = 0; uint64_t byt = 0;
    for (int k = 0; k < 8; ++k) {
        int pos = k, last = -3;
        while (pos < 8) {
            uint32_t m = b >> pos;
            if (!m) break;
            int s = pos + __ffs((int)m) - 1;
            last = s;
            pos = s + REFR + 1;
        }
        int q = last - 2; if (q < 0) q = 0;
        sel |= (uint32_t)q << (4 * k);
        byt |= (uint64_t)q << (8 * k);
    }
    s_sel[b] = sel; s_byt[b] = byt;
    __syncthreads();
}

// byte-packed (2 regs) -> nibble-packed u32 (q values are all <= 7)
__device__ __forceinline__ uint32_t nib_compress(uint32_t lo, uint32_t hi) {
    uint32_t t1 = lo | (lo >> 4);
    uint32_t t2 = hi | (hi >> 4);
    return __byte_perm(t1, 0, 0x4420) | (__byte_perm(t2, 0, 0x4420) << 16);
}

// Pass 1: per (chain-quad, chunk): read x, build 4 sign masks + 4 chunk maps.
__global__ void __launch_bounds__(256) pass1_mask_map(const float4* __restrict__ x4) {
    __shared__ uint32_t s_sel[256];
    __shared__ uint64_t s_byt[256];
    build_luts(s_sel, s_byt);

    int tid  = blockIdx.x * 256 + threadIdx.x;   // 0 .. NQ*NC-1
    int quad = tid & (NQ - 1);
    int c    = tid >> 11;                        // / NQ
    int b    = quad >> 6;                        // / (NN/4)
    int nq   = quad & 63;

    const float4* px = x4 + ((size_t)b * TT + (size_t)c * CHUNK) * (NN / 4) + nq;

    uint64_t m0 = 0, m1 = 0, m2 = 0, m3 = 0;
    uint32_t S0l, S0h, S1l, S1h, S2l, S2h, S3l, S3h;

    // byte 7 first (right fold: S = m7), then fold m6..m0 in.
    {
        uint32_t b0 = 0, b1 = 0, b2 = 0, b3 = 0;
#pragma unroll
        for (int i = 0; i < 8; ++i) {
            float4 v = px[(size_t)(56 + i) * (NN / 4)];
            if (v.x > 0.0f) b0 |= 1u << i;
            if (v.y > 0.0f) b1 |= 1u << i;
            if (v.z > 0.0f) b2 |= 1u << i;
            if (v.w > 0.0f) b3 |= 1u << i;
        }
        m0 |= (uint64_t)b0 << 56; m1 |= (uint64_t)b1 << 56;
        m2 |= (uint64_t)b2 << 56; m3 |= (uint64_t)b3 << 56;
        uint64_t t;
        t = s_byt[b0]; S0l = (uint32_t)t; S0h = (uint32_t)(t >> 32);
        t = s_byt[b1]; S1l = (uint32_t)t; S1h = (uint32_t)(t >> 32);
        t = s_byt[b2]; S2l = (uint32_t)t; S2h = (uint32_t)(t >> 32);
        t = s_byt[b3]; S3l = (uint32_t)t; S3h = (uint32_t)(t >> 32);
    }
#pragma unroll
    for (int j = 6; j >= 0; --j) {
        uint32_t b0 = 0, b1 = 0, b2 = 0, b3 = 0;
#pragma unroll
        for (int i = 0; i < 8; ++i) {
            float4 v = px[(size_t)(j * 8 + i) * (NN / 4)];
            if (v.x > 0.0f) b0 |= 1u << i;
            if (v.y > 0.0f) b1 |= 1u << i;
            if (v.z > 0.0f) b2 |= 1u << i;
            if (v.w > 0.0f) b3 |= 1u << i;
        }
        m0 |= (uint64_t)b0 << (8 * j); m1 |= (uint64_t)b1 << (8 * j);
        m2 |= (uint64_t)b2 << (8 * j); m3 |= (uint64_t)b3 << (8 * j);
        uint32_t sel, nl, nh;
        sel = s_sel[b0]; nl = __byte_perm(S0l, S0h, sel); nh = __byte_perm(S0l, S0h, sel >> 16); S0l = nl; S0h = nh;
        sel = s_sel[b1]; nl = __byte_perm(S1l, S1h, sel); nh = __byte_perm(S1l, S1h, sel >> 16); S1l = nl; S1h = nh;
        sel = s_sel[b2]; nl = __byte_perm(S2l, S2h, sel); nh = __byte_perm(S2l, S2h, sel >> 16); S2l = nl; S2h = nh;
        sel = s_sel[b3]; nl = __byte_perm(S3l, S3h, sel); nh = __byte_perm(S3l, S3h, sel >> 16); S3l = nl; S3h = nh;
    }

    g_mask2[c][quad * 2]     = make_ulonglong2(m0, m1);
    g_mask2[c][quad * 2 + 1] = make_ulonglong2(m2, m3);
    g_map4[c][quad] = make_uint4(nib_compress(S0l, S0h), nib_compress(S1l, S1h),
                                 nib_compress(S2l, S2h), nib_compress(S3l, S3h));
}

// Pass 2: per chain — chain the 64 nibble-packed chunk maps.
__global__ void __launch_bounds__(256) pass2_compose() {
    int bn = blockIdx.x * 256 + threadIdx.x;     // 0 .. BN-1
    const uint32_t* maps = (const uint32_t*)g_map4;   // flat [NC][BN]
    uint8_t* qin = (uint8_t*)g_qin4;                  // flat [NC][BN]
    uint32_t q = 0;
#pragma unroll
    for (int base = 0; base < NC; base += 16) {
        uint32_t m[16];
#pragma unroll
        for (int j = 0; j < 16; ++j) m[j] = maps[(base + j) * BN + bn];
#pragma unroll
        for (int j = 0; j < 16; ++j) {
            qin[(base + j) * BN + bn] = (uint8_t)q;
            q = (m[j] >> (q * 4)) & 7u;
        }
    }
}

// Pass 3 (R2-proven structure): one thread per (chain, chunk).
// Register-only greedy rebuild, then 64 scalar coalesced stores (128B/warp/step).
__global__ void __launch_bounds__(256) pass3_emit(float* __restrict__ out) {
    int tid = blockIdx.x * 256 + threadIdx.x;    // 0 .. BN*NC-1
    int bn  = tid & (BN - 1);
    int c   = tid >> 13;                         // / BN

    const uint64_t* mask_flat = (const uint64_t*)g_mask2;  // flat [NC][BN]
    const uint8_t*  qin_flat  = (const uint8_t*)g_qin4;    // flat [NC][BN]

    uint64_t mask = mask_flat[c * BN + bn];
    int pos = qin_flat[c * BN + bn];

    uint64_t spikes = 0;
    while (pos < CHUNK) {
        uint64_t m = mask >> pos;
        if (!m) break;
        int s = pos + __ffsll((long long)m) - 1;
        spikes |= 1ull << s;
        pos = s + REFR + 1;
    }

    int b = bn >> 8;
    int n = bn & (NN - 1);
    float* po = out + ((size_t)b * TT + (size_t)c * CHUNK) * NN + n;
#pragma unroll 16
    for (int i = 0; i < CHUNK; ++i) {
        uint32_t bit = (uint32_t)(spikes >> i) & 1u;
        po[(size_t)i * NN] = (float)bit;          // coalesced 128B stores
    }
}

extern "C" void kernel_launch(void* const* d_in, const int* in_sizes, int n_in,
                              void* d_out, int out_size) {
    (void)in_sizes; (void)n_in; (void)out_size;
    const float4* x4 = (const float4*)d_in[0];
    float* out = (float*)d_out;

    const int threads = 256;
    const int grid_p1 = (NQ * NC) / threads;     // 512 blocks
    const int grid_p2 = BN / threads;            // 32 blocks
    const int grid_p3 = (BN * NC) / threads;     // 2048 blocks

    pass1_mask_map<<<grid_p1, threads>>>(x4);
    pass2_compose<<<grid_p2, threads>>>();
    pass3_emit<<<grid_p3, threads>>>(out);
}

// round 11
// speedup vs baseline: 1.3944x; 1.0325x over previous
#include <cuda_runtime.h>
#include <cstdint>

// x [B=32, T=4096, N=256] float32 -> z same shape.
#define BB 32
#define TT 4096
#define NN 256
#define BN (BB * NN)          // 8192 chains
#define NP (BN / 2)           // 4096 chain-pairs
#define CHUNK 64
#define NC (TT / CHUNK)       // 64 chunks
#define REFR 5

// Static scratch (~6.5 MB, L2-resident)
__device__ ulonglong2 g_mask2[NC][NP];    // per-chain 64-bit sign masks (pairs)
__device__ uint2      g_map2[NC][NP];     // per-chain nibble-packed chunk map
__device__ uint8_t    g_qin[NC][BN];      // incoming q per (chunk, chain)

// Byte-level automaton LUTs (blockDim.x == 256) — used by pass1 only.
// For byte b, incoming state k (0..7): greedy spikes, q_out = max(0, last-2).
// s_sel[b]: nibble k = q_out(k) (PRMT-selector-ready); s_byt[b]: byte k = q_out(k).
__device__ __forceinline__ void build_luts(uint32_t* s_sel, uint64_t* s_byt) {
    const uint32_t b = threadIdx.x;
    uint32_t sel = 0; uint64_t byt = 0;
    for (int k = 0; k < 8; ++k) {
        int pos = k, last = -3;
        while (pos < 8) {
            uint32_t m = b >> pos;
            if (!m) break;
            int s = pos + __ffs((int)m) - 1;
            last = s;
            pos = s + REFR + 1;
        }
        int q = last - 2; if (q < 0) q = 0;
        sel |= (uint32_t)q << (4 * k);
        byt |= (uint64_t)q << (8 * k);
    }
    s_sel[b] = sel; s_byt[b] = byt;
    __syncthreads();
}

// byte-packed (2 regs) -> nibble-packed u32 (q values are all <= 7)
__device__ __forceinline__ uint32_t nib_compress(uint32_t lo, uint32_t hi) {
    uint32_t t1 = lo | (lo >> 4);
    uint32_t t2 = hi | (hi >> 4);
    return __byte_perm(t1, 0, 0x4420) | (__byte_perm(t2, 0, 0x4420) << 16);
}

// Pass 1: one thread per (chain-pair, chunk): read x (float2), build 2 sign
// masks + 2 nibble-packed chunk maps via the PRMT byte-fold.
__global__ void __launch_bounds__(256, 6) pass1_mask_map(const float2* __restrict__ x2) {
    __shared__ uint32_t s_sel[256];
    __shared__ uint64_t s_byt[256];
    build_luts(s_sel, s_byt);

    int tid  = blockIdx.x * 256 + threadIdx.x;   // 0 .. NP*NC-1
    int pair = tid & (NP - 1);
    int c    = tid >> 12;                        // / NP
    int b    = pair >> 7;                        // / (NN/2)
    int np   = pair & 127;

    const float2* px = x2 + ((size_t)b * TT + (size_t)c * CHUNK) * (NN / 2) + np;

    uint64_t m0 = 0, m1 = 0;
    uint32_t S0l, S0h, S1l, S1h;

    // byte 7 first (right fold: S = m7), then fold m6..m0 in.
    {
        uint32_t b0 = 0, b1 = 0;
#pragma unroll
        for (int i = 0; i < 8; ++i) {
            float2 v = px[(size_t)(56 + i) * (NN / 2)];
            if (v.x > 0.0f) b0 |= 1u << i;
            if (v.y > 0.0f) b1 |= 1u << i;
        }
        m0 |= (uint64_t)b0 << 56; m1 |= (uint64_t)b1 << 56;
        uint64_t t;
        t = s_byt[b0]; S0l = (uint32_t)t; S0h = (uint32_t)(t >> 32);
        t = s_byt[b1]; S1l = (uint32_t)t; S1h = (uint32_t)(t >> 32);
    }
#pragma unroll
    for (int j = 6; j >= 0; --j) {
        uint32_t b0 = 0, b1 = 0;
#pragma unroll
        for (int i = 0; i < 8; ++i) {
            float2 v = px[(size_t)(j * 8 + i) * (NN / 2)];
            if (v.x > 0.0f) b0 |= 1u << i;
            if (v.y > 0.0f) b1 |= 1u << i;
        }
        m0 |= (uint64_t)b0 << (8 * j);
        m1 |= (uint64_t)b1 << (8 * j);
        uint32_t sel, nl, nh;
        sel = s_sel[b0]; nl = __byte_perm(S0l, S0h, sel); nh = __byte_perm(S0l, S0h, sel >> 16); S0l = nl; S0h = nh;
        sel = s_sel[b1]; nl = __byte_perm(S1l, S1h, sel); nh = __byte_perm(S1l, S1h, sel >> 16); S1l = nl; S1h = nh;
    }

    g_mask2[c][pair] = make_ulonglong2(m0, m1);
    g_map2[c][pair]  = make_uint2(nib_compress(S0l, S0h), nib_compress(S1l, S1h));
}

// Pass 2: per chain — chain the 64 nibble-packed chunk maps.
__global__ void __launch_bounds__(256) pass2_compose() {
    int bn = blockIdx.x * 256 + threadIdx.x;     // 0 .. BN-1
    const uint32_t* maps = (const uint32_t*)g_map2;   // flat [NC][BN]
    uint8_t* qin = (uint8_t*)g_qin;                   // flat [NC][BN]
    uint32_t q = 0;
#pragma unroll
    for (int base = 0; base < NC; base += 16) {
        uint32_t m[16];
#pragma unroll
        for (int j = 0; j < 16; ++j) m[j] = maps[(base + j) * BN + bn];
#pragma unroll
        for (int j = 0; j < 16; ++j) {
            qin[(base + j) * BN + bn] = (uint8_t)q;
            q = (m[j] >> (q * 4)) & 7u;
        }
    }
}

// Pass 3 (proven structure): one thread per (chain, chunk).
// Register-only greedy rebuild, then 64 scalar coalesced streaming stores.
__global__ void __launch_bounds__(256) pass3_emit(float* __restrict__ out) {
    int tid = blockIdx.x * 256 + threadIdx.x;    // 0 .. BN*NC-1
    int bn  = tid & (BN - 1);
    int c   = tid >> 13;                         // / BN

    const uint64_t* mask_flat = (const uint64_t*)g_mask2;  // flat [NC][BN]
    const uint8_t*  qin_flat  = (const uint8_t*)g_qin;     // flat [NC][BN]

    uint64_t mask = mask_flat[c * BN + bn];
    int pos = qin_flat[c * BN + bn];

    uint64_t spikes = 0;
    while (pos < CHUNK) {
        uint64_t m = mask >> pos;
        if (!m) break;
        int s = pos + __ffsll((long long)m) - 1;
        spikes |= 1ull << s;
        pos = s + REFR + 1;
    }

    int b = bn >> 8;
    int n = bn & (NN - 1);
    float* po = out + ((size_t)b * TT + (size_t)c * CHUNK) * NN + n;
#pragma unroll 16
    for (int i = 0; i < CHUNK; ++i) {
        uint32_t bit = (uint32_t)(spikes >> i) & 1u;
        __stcs(po + (size_t)i * NN, (float)bit);   // streaming: evict-first
    }
}

extern "C" void kernel_launch(void* const* d_in, const int* in_sizes, int n_in,
                              void* d_out, int out_size) {
    (void)in_sizes; (void)n_in; (void)out_size;
    const float2* x2 = (const float2*)d_in[0];
    float* out = (float*)d_out;

    const int threads = 256;
    const int grid_p1 = (NP * NC) / threads;     // 1024 blocks
    const int grid_p2 = BN / threads;            // 32 blocks
    const int grid_p3 = (BN * NC) / threads;     // 2048 blocks

    pass1_mask_map<<<grid_p1, threads>>>(x2);
    pass2_compose<<<grid_p2, threads>>>();
    pass3_emit<<<grid_p3, threads>>>(out);
}